// round 9
// baseline (speedup 1.0000x reference)
#include <cuda_runtime.h>
#include <cuda_fp16.h>
#include <math.h>
#include <stdint.h>

#define NN 1024
#define HH 64

__device__ float g_A[NN * HH];     // z_c @ W1[:64]
__device__ float g_B[NN * HH];     // z_d @ W1[64:] + b1
__device__ float g_T1[NN * NN];
__device__ double g_acc;
__device__ int    g_cnt;

// ---------------------------------------------------------------------------
#define MMA16816(c, a0, a1, a2, a3, b0, b1)                                   \
    asm("mma.sync.aligned.m16n8k16.row.col.f32.f16.f16.f32 "                  \
        "{%0,%1,%2,%3}, {%4,%5,%6,%7}, {%8,%9}, {%0,%1,%2,%3};"               \
        : "+f"((c)[0]), "+f"((c)[1]), "+f"((c)[2]), "+f"((c)[3])              \
        : "r"(a0), "r"(a1), "r"(a2), "r"(a3), "r"(b0), "r"(b1))

__device__ __forceinline__ uint32_t pack_h2(float e0, float e1) {
    uint32_t r;
    asm("cvt.rn.f16x2.f32 %0, %1, %2;" : "=r"(r) : "f"(e1), "f"(e0));
    return r;
}
__device__ __forceinline__ float hi_part(float x) {   // top 10 mantissa bits
    return __uint_as_float(__float_as_uint(x) & 0xFFFFE000u);
}

// ---------------------------------------------------------------------------
// Kernel 1: precompute A and B (+ zero the global accumulators each launch)
// ---------------------------------------------------------------------------
__global__ void prep_kernel(const float* __restrict__ zc,
                            const float* __restrict__ zd,
                            const float* __restrict__ W1,
                            const float* __restrict__ b1) {
    if (blockIdx.x == 0 && blockIdx.y == 0 && threadIdx.x == 0) {
        g_acc = 0.0;
        g_cnt = 0;
    }
    int which = blockIdx.y;
    int row = blockIdx.x * 4 + (threadIdx.x >> 6);
    int col = threadIdx.x & 63;
    const float* src = which ? zd : zc;
    const float* w   = W1 + (which ? 64 * HH : 0);
    // 4 independent FMA chains (depth 16 instead of 64)
    float s0 = which ? b1[col] : 0.0f, s1 = 0.f, s2 = 0.f, s3 = 0.f;
#pragma unroll
    for (int k = 0; k < 64; k += 4) {
        s0 = fmaf(src[row * 64 + k],     w[(k) * HH + col],     s0);
        s1 = fmaf(src[row * 64 + k + 1], w[(k + 1) * HH + col], s1);
        s2 = fmaf(src[row * 64 + k + 2], w[(k + 2) * HH + col], s2);
        s3 = fmaf(src[row * 64 + k + 3], w[(k + 3) * HH + col], s3);
    }
    float s = (s0 + s1) + (s2 + s3);
    if (which) g_B[row * HH + col] = s;
    else       g_A[row * HH + col] = s;
}

// ---------------------------------------------------------------------------
// Kernel 2: pairwise MLP via HMMA, split-fp16 3-term fp32 emulation.
// R9: A-block values hoisted into registers before the i-loop (loop-invariant)
//     -> main loop has ZERO shared-memory traffic; fragment build is a short
//     all-register chain. Bi loads remain software-pipelined.
// ---------------------------------------------------------------------------
#define JSTRIDE 18   // CTAs per j-block; grid = 16 * 18 = 288

__global__ __launch_bounds__(128, 2) void pair_mma_kernel(
    const float* __restrict__ W2, const float* __restrict__ b2,
    const float* __restrict__ Wo, const float* __restrict__ bo_p) {
    __shared__ float sAT[64 * 68];   // [k][m], stride 68; used only in prologue

    const int tid  = threadIdx.x;
    const int lane = tid & 31;
    const int wid  = tid >> 5;
    const int gid  = lane >> 2;      // 0..7
    const int tid4 = lane & 3;       // 0..3

    const int jb  = blockIdx.x / JSTRIDE;    // 0..15
    const int s0i = blockIdx.x % JSTRIDE;    // starting i
    const int j0  = jb * 64;

    // ---- stage A block transposed: sAT[k*68 + m] = g_A[(j0+m)*64 + k] ----
    for (int idx = tid; idx < 4096; idx += 128) {
        int m = idx >> 6, k = idx & 63;
        sAT[k * 68 + m] = g_A[(size_t)j0 * 64 + idx];
    }

    // ---- preload W2 fragments (hi/lo split) into registers ----
    uint32_t Bh[4][8][2], Bl[4][8][2];
#pragma unroll
    for (int ks = 0; ks < 4; ++ks) {
#pragma unroll
        for (int nt = 0; nt < 8; ++nt) {
            int k0 = 16 * ks + 2 * tid4;
            int n  = 8 * nt + gid;
            float w00 = W2[(k0 + 0) * HH + n], w01 = W2[(k0 + 1) * HH + n];
            float w10 = W2[(k0 + 8) * HH + n], w11 = W2[(k0 + 9) * HH + n];
            float h00 = hi_part(w00), h01 = hi_part(w01);
            float h10 = hi_part(w10), h11 = hi_part(w11);
            Bh[ks][nt][0] = pack_h2(h00, h01);
            Bh[ks][nt][1] = pack_h2(h10, h11);
            Bl[ks][nt][0] = pack_h2(w00 - h00, w01 - h01);
            Bl[ks][nt][1] = pack_h2(w10 - h10, w11 - h11);
        }
    }

    // ---- per-thread epilogue constants ----
    float2 b2r[8], wor[8];
#pragma unroll
    for (int nt = 0; nt < 8; ++nt) {
        int n = 8 * nt + 2 * tid4;
        b2r[nt] = make_float2(b2[n], b2[n + 1]);
        wor[nt] = make_float2(Wo[n], Wo[n + 1]);
    }
    const float bo = bo_p[0];

    const int m0 = wid * 16 + gid;   // this thread's first row in j-block

    __syncthreads();                 // sAT ready

    // ---- hoist this thread's A values into registers (loop-invariant) ----
    // aR[ks][v]: v = {m0/k0, m0/k0+1, m0/k0+8, m0/k0+9, m0+8/k0, ..., m0+8/k0+9}
    float aR[4][8];
#pragma unroll
    for (int ks = 0; ks < 4; ++ks) {
        const int k0 = 16 * ks + 2 * tid4;
        const float* cL = sAT + k0 * 68 + m0;
        aR[ks][0] = cL[0];
        aR[ks][1] = cL[68];
        aR[ks][2] = cL[8 * 68];
        aR[ks][3] = cL[9 * 68];
        aR[ks][4] = cL[8];
        aR[ks][5] = cL[68 + 8];
        aR[ks][6] = cL[8 * 68 + 8];
        aR[ks][7] = cL[9 * 68 + 8];
    }

    // ---- prime the Bi pipeline for i = s0i ----
    float2 nbiL[4], nbiH[4];
    {
        const float* Bi = g_B + (size_t)s0i * 64;
#pragma unroll
        for (int ks = 0; ks < 4; ++ks) {
            const int k0 = 16 * ks + 2 * tid4;
            nbiL[ks] = *(const float2*)(Bi + k0);
            nbiH[ks] = *(const float2*)(Bi + k0 + 8);
        }
    }

    for (int i = s0i; i < NN; i += JSTRIDE) {
        float2 biL[4], biH[4];
#pragma unroll
        for (int ks = 0; ks < 4; ++ks) { biL[ks] = nbiL[ks]; biH[ks] = nbiH[ks]; }

        if (i + JSTRIDE < NN) {
            const float* Bn = g_B + (size_t)(i + JSTRIDE) * 64;
#pragma unroll
            for (int ks = 0; ks < 4; ++ks) {
                const int k0 = 16 * ks + 2 * tid4;
                nbiL[ks] = *(const float2*)(Bn + k0);
                nbiH[ks] = *(const float2*)(Bn + k0 + 8);
            }
        }

        float acc[8][4];
#pragma unroll
        for (int nt = 0; nt < 8; ++nt)
#pragma unroll
            for (int q = 0; q < 4; ++q) acc[nt][q] = 0.0f;

#pragma unroll
        for (int ks = 0; ks < 4; ++ks) {
            // all-register fragment build
            float h0 = fmaxf(aR[ks][0] + biL[ks].x, 0.f);
            float h1 = fmaxf(aR[ks][1] + biL[ks].y, 0.f);
            float h2 = fmaxf(aR[ks][2] + biH[ks].x, 0.f);
            float h3 = fmaxf(aR[ks][3] + biH[ks].y, 0.f);
            float h4 = fmaxf(aR[ks][4] + biL[ks].x, 0.f);
            float h5 = fmaxf(aR[ks][5] + biL[ks].y, 0.f);
            float h6 = fmaxf(aR[ks][6] + biH[ks].x, 0.f);
            float h7 = fmaxf(aR[ks][7] + biH[ks].y, 0.f);

            float g0 = hi_part(h0), g1 = hi_part(h1), g2 = hi_part(h2),
                  g3 = hi_part(h3), g4 = hi_part(h4), g5 = hi_part(h5),
                  g6 = hi_part(h6), g7 = hi_part(h7);

            uint32_t a0h = pack_h2(g0, g1);
            uint32_t a1h = pack_h2(g4, g5);
            uint32_t a2h = pack_h2(g2, g3);
            uint32_t a3h = pack_h2(g6, g7);
            uint32_t a0l = pack_h2(h0 - g0, h1 - g1);
            uint32_t a1l = pack_h2(h4 - g4, h5 - g5);
            uint32_t a2l = pack_h2(h2 - g2, h3 - g3);
            uint32_t a3l = pack_h2(h6 - g6, h7 - g7);

#pragma unroll
            for (int nt = 0; nt < 8; ++nt)
                MMA16816(acc[nt], a0h, a1h, a2h, a3h,
                         Bh[ks][nt][0], Bh[ks][nt][1]);
#pragma unroll
            for (int nt = 0; nt < 8; ++nt)
                MMA16816(acc[nt], a0h, a1h, a2h, a3h,
                         Bl[ks][nt][0], Bl[ks][nt][1]);
#pragma unroll
            for (int nt = 0; nt < 8; ++nt)
                MMA16816(acc[nt], a0l, a1l, a2l, a3l,
                         Bh[ks][nt][0], Bh[ks][nt][1]);
        }

        // epilogue: rows m0 (c0,c1) and m0+8 (c2,c3)
        float sA0 = 0.f, sA1 = 0.f;
#pragma unroll
        for (int nt = 0; nt < 8; ++nt) {
            sA0 = fmaf(fmaxf(acc[nt][0] + b2r[nt].x, 0.f), wor[nt].x, sA0);
            sA0 = fmaf(fmaxf(acc[nt][1] + b2r[nt].y, 0.f), wor[nt].y, sA0);
            sA1 = fmaf(fmaxf(acc[nt][2] + b2r[nt].x, 0.f), wor[nt].x, sA1);
            sA1 = fmaf(fmaxf(acc[nt][3] + b2r[nt].y, 0.f), wor[nt].y, sA1);
        }
        sA0 += __shfl_xor_sync(0xffffffffu, sA0, 1);
        sA0 += __shfl_xor_sync(0xffffffffu, sA0, 2);
        sA1 += __shfl_xor_sync(0xffffffffu, sA1, 1);
        sA1 += __shfl_xor_sync(0xffffffffu, sA1, 2);
        if (tid4 == 0) {
            g_T1[(size_t)i * NN + j0 + m0]     = sA0 + bo;
            g_T1[(size_t)i * NN + j0 + m0 + 8] = sA1 + bo;
        }
    }
}

// ---------------------------------------------------------------------------
// Kernel 3: per-row logsumexp + diagonal + fused final reduction.
// ---------------------------------------------------------------------------
__global__ void lse_kernel(float* out) {
    __shared__ float sm[8], ss[8];
    const int i = blockIdx.x, tid = threadIdx.x;
    const int lane = tid & 31, wid = tid >> 5;
    const float4 v = ((const float4*)(g_T1 + (size_t)i * NN))[tid];

    float m = fmaxf(fmaxf(v.x, v.y), fmaxf(v.z, v.w));
#pragma unroll
    for (int o = 16; o > 0; o >>= 1)
        m = fmaxf(m, __shfl_xor_sync(0xffffffffu, m, o));
    if (lane == 0) sm[wid] = m;
    __syncthreads();
    float bm = sm[0];
#pragma unroll
    for (int w = 1; w < 8; ++w) bm = fmaxf(bm, sm[w]);

    float s = __expf(v.x - bm) + __expf(v.y - bm) +
              __expf(v.z - bm) + __expf(v.w - bm);
#pragma unroll
    for (int o = 16; o > 0; o >>= 1)
        s += __shfl_xor_sync(0xffffffffu, s, o);
    if (lane == 0) ss[wid] = s;
    __syncthreads();

    if (tid == 0) {
        float tot = ss[0] + ss[1] + ss[2] + ss[3] +
                    ss[4] + ss[5] + ss[6] + ss[7];
        double lse  = (double)bm + log((double)tot);
        double diag = (double)g_T1[(size_t)i * NN + i];
        atomicAdd(&g_acc, diag - lse);
        __threadfence();
        if (atomicAdd(&g_cnt, 1) == NN - 1) {
            double acc = atomicAdd(&g_acc, 0.0);   // forced atomic read
            out[0] = (float)(acc / NN + log((double)NN));
        }
    }
}

// ---------------------------------------------------------------------------
extern "C" void kernel_launch(void* const* d_in, const int* in_sizes, int n_in,
                              void* d_out, int out_size) {
    const float* z_c = (const float*)d_in[0];
    const float* z_d = (const float*)d_in[1];
    const float* W1  = (const float*)d_in[2];
    const float* b1  = (const float*)d_in[3];
    const float* W2  = (const float*)d_in[4];
    const float* b2  = (const float*)d_in[5];
    const float* Wo  = (const float*)d_in[6];
    const float* bo  = (const float*)d_in[7];
    float* out = (float*)d_out;

    prep_kernel<<<dim3(NN / 4, 2), 256>>>(z_c, z_d, W1, b1);
    pair_mma_kernel<<<16 * JSTRIDE, 128>>>(W2, b2, Wo, bo);
    lse_kernel<<<NN, 256>>>(out);
}

// round 10
// speedup vs baseline: 1.1470x; 1.1470x over previous
#include <cuda_runtime.h>
#include <cuda_fp16.h>
#include <math.h>
#include <stdint.h>

#define NN 1024
#define HH 64

__device__ float g_A[NN * HH];     // z_c @ W1[:64]
__device__ float g_B[NN * HH];     // z_d @ W1[64:] + b1
__device__ float g_T1[NN * NN];
__device__ double g_acc;
__device__ int    g_cnt;

// ---------------------------------------------------------------------------
#define MMA16816(c, a0, a1, a2, a3, b0, b1)                                   \
    asm("mma.sync.aligned.m16n8k16.row.col.f32.f16.f16.f32 "                  \
        "{%0,%1,%2,%3}, {%4,%5,%6,%7}, {%8,%9}, {%0,%1,%2,%3};"               \
        : "+f"((c)[0]), "+f"((c)[1]), "+f"((c)[2]), "+f"((c)[3])              \
        : "r"(a0), "r"(a1), "r"(a2), "r"(a3), "r"(b0), "r"(b1))

__device__ __forceinline__ uint32_t pack_h2(float e0, float e1) {
    uint32_t r;
    asm("cvt.rn.f16x2.f32 %0, %1, %2;" : "=r"(r) : "f"(e1), "f"(e0));
    return r;
}
__device__ __forceinline__ float hi_part(float x) {   // top 10 mantissa bits
    return __uint_as_float(__float_as_uint(x) & 0xFFFFE000u);
}

// ---------------------------------------------------------------------------
// Kernel 1: precompute A and B. W1-half staged in smem (kills redundant
// strided global loads); 4 independent FMA chains.
// ---------------------------------------------------------------------------
__global__ void prep_kernel(const float* __restrict__ zc,
                            const float* __restrict__ zd,
                            const float* __restrict__ W1,
                            const float* __restrict__ b1) {
    __shared__ float sW[64 * 64];    // 16 KB: this half of W1
    const int tid = threadIdx.x;
    if (blockIdx.x == 0 && blockIdx.y == 0 && tid == 0) {
        g_acc = 0.0;
        g_cnt = 0;
    }
    int which = blockIdx.y;
    const float* w = W1 + (which ? 64 * HH : 0);
    for (int t = tid; t < 4096; t += 256) sW[t] = w[t];
    __syncthreads();

    int row = blockIdx.x * 4 + (tid >> 6);
    int col = tid & 63;
    const float* src = which ? zd : zc;
    float s0 = which ? b1[col] : 0.0f, s1 = 0.f, s2 = 0.f, s3 = 0.f;
#pragma unroll
    for (int k = 0; k < 64; k += 4) {
        s0 = fmaf(src[row * 64 + k],     sW[(k) * HH + col],     s0);
        s1 = fmaf(src[row * 64 + k + 1], sW[(k + 1) * HH + col], s1);
        s2 = fmaf(src[row * 64 + k + 2], sW[(k + 2) * HH + col], s2);
        s3 = fmaf(src[row * 64 + k + 3], sW[(k + 3) * HH + col], s3);
    }
    float s = (s0 + s1) + (s2 + s3);
    if (which) g_B[row * HH + col] = s;
    else       g_A[row * HH + col] = s;
}

// ---------------------------------------------------------------------------
// Kernel 2: pairwise MLP via HMMA, 2-term split emulation:
//   h = hh + hl (exact to ~2^-21), W2 single fp16 rounding.
//   D = hh@Wf + hl@Wf  -> 64 MMAs/iter (was 96).
// occ 2, W fragments in registers, Bi software-pipelined (R8 structure).
// ---------------------------------------------------------------------------
#define JSTRIDE 18   // CTAs per j-block; grid = 16 * 18 = 288

__global__ __launch_bounds__(128, 2) void pair_mma_kernel(
    const float* __restrict__ W2, const float* __restrict__ b2,
    const float* __restrict__ Wo, const float* __restrict__ bo_p) {
    __shared__ float sAT[64 * 68];   // [k][m], stride 68 (conflict-free frag reads)

    const int tid  = threadIdx.x;
    const int lane = tid & 31;
    const int wid  = tid >> 5;
    const int gid  = lane >> 2;      // 0..7
    const int tid4 = lane & 3;       // 0..3

    const int jb  = blockIdx.x / JSTRIDE;    // 0..15
    const int s0i = blockIdx.x % JSTRIDE;    // starting i
    const int j0  = jb * 64;

    // ---- stage A block transposed: sAT[k*68 + m] = g_A[(j0+m)*64 + k] ----
    for (int idx = tid; idx < 4096; idx += 128) {
        int m = idx >> 6, k = idx & 63;
        sAT[k * 68 + m] = g_A[(size_t)j0 * 64 + idx];
    }

    // ---- preload W2 fragments (single fp16 rounding) into registers ----
    uint32_t Bf[4][8][2];
#pragma unroll
    for (int ks = 0; ks < 4; ++ks) {
#pragma unroll
        for (int nt = 0; nt < 8; ++nt) {
            int k0 = 16 * ks + 2 * tid4;
            int n  = 8 * nt + gid;
            Bf[ks][nt][0] = pack_h2(W2[(k0 + 0) * HH + n], W2[(k0 + 1) * HH + n]);
            Bf[ks][nt][1] = pack_h2(W2[(k0 + 8) * HH + n], W2[(k0 + 9) * HH + n]);
        }
    }

    // ---- per-thread epilogue constants ----
    float2 b2r[8], wor[8];
#pragma unroll
    for (int nt = 0; nt < 8; ++nt) {
        int n = 8 * nt + 2 * tid4;
        b2r[nt] = make_float2(b2[n], b2[n + 1]);
        wor[nt] = make_float2(Wo[n], Wo[n + 1]);
    }
    const float bo = bo_p[0];

    const int m0 = wid * 16 + gid;   // this thread's first row in j-block

    __syncthreads();                 // sAT ready (only barrier in kernel)

    // ---- prime the Bi pipeline for i = s0i ----
    float2 nbiL[4], nbiH[4];
    {
        const float* Bi = g_B + (size_t)s0i * 64;
#pragma unroll
        for (int ks = 0; ks < 4; ++ks) {
            const int k0 = 16 * ks + 2 * tid4;
            nbiL[ks] = *(const float2*)(Bi + k0);
            nbiH[ks] = *(const float2*)(Bi + k0 + 8);
        }
    }

    for (int i = s0i; i < NN; i += JSTRIDE) {
        float2 biL[4], biH[4];
#pragma unroll
        for (int ks = 0; ks < 4; ++ks) { biL[ks] = nbiL[ks]; biH[ks] = nbiH[ks]; }

        if (i + JSTRIDE < NN) {
            const float* Bn = g_B + (size_t)(i + JSTRIDE) * 64;
#pragma unroll
            for (int ks = 0; ks < 4; ++ks) {
                const int k0 = 16 * ks + 2 * tid4;
                nbiL[ks] = *(const float2*)(Bn + k0);
                nbiH[ks] = *(const float2*)(Bn + k0 + 8);
            }
        }

        float acc[8][4];
#pragma unroll
        for (int nt = 0; nt < 8; ++nt)
#pragma unroll
            for (int q = 0; q < 4; ++q) acc[nt][q] = 0.0f;

#pragma unroll
        for (int ks = 0; ks < 4; ++ks) {
            const int k0 = 16 * ks + 2 * tid4;

            const float* cL = sAT + k0 * 68 + m0;
            float h0 = fmaxf(cL[0]        + biL[ks].x, 0.f);
            float h1 = fmaxf(cL[68]       + biL[ks].y, 0.f);
            float h2 = fmaxf(cL[8 * 68]   + biH[ks].x, 0.f);
            float h3 = fmaxf(cL[9 * 68]   + biH[ks].y, 0.f);
            float h4 = fmaxf(cL[8]        + biL[ks].x, 0.f);
            float h5 = fmaxf(cL[68 + 8]   + biL[ks].y, 0.f);
            float h6 = fmaxf(cL[8*68 + 8] + biH[ks].x, 0.f);
            float h7 = fmaxf(cL[9*68 + 8] + biH[ks].y, 0.f);

            float g0 = hi_part(h0), g1 = hi_part(h1), g2 = hi_part(h2),
                  g3 = hi_part(h3), g4 = hi_part(h4), g5 = hi_part(h5),
                  g6 = hi_part(h6), g7 = hi_part(h7);

            uint32_t a0h = pack_h2(g0, g1);
            uint32_t a1h = pack_h2(g4, g5);
            uint32_t a2h = pack_h2(g2, g3);
            uint32_t a3h = pack_h2(g6, g7);
            uint32_t a0l = pack_h2(h0 - g0, h1 - g1);
            uint32_t a1l = pack_h2(h4 - g4, h5 - g5);
            uint32_t a2l = pack_h2(h2 - g2, h3 - g3);
            uint32_t a3l = pack_h2(h6 - g6, h7 - g7);

            // pass 1: hh * Wf
#pragma unroll
            for (int nt = 0; nt < 8; ++nt)
                MMA16816(acc[nt], a0h, a1h, a2h, a3h,
                         Bf[ks][nt][0], Bf[ks][nt][1]);
            // pass 2: hl * Wf
#pragma unroll
            for (int nt = 0; nt < 8; ++nt)
                MMA16816(acc[nt], a0l, a1l, a2l, a3l,
                         Bf[ks][nt][0], Bf[ks][nt][1]);
        }

        // epilogue: rows m0 (c0,c1) and m0+8 (c2,c3)
        float sA0 = 0.f, sA1 = 0.f;
#pragma unroll
        for (int nt = 0; nt < 8; ++nt) {
            sA0 = fmaf(fmaxf(acc[nt][0] + b2r[nt].x, 0.f), wor[nt].x, sA0);
            sA0 = fmaf(fmaxf(acc[nt][1] + b2r[nt].y, 0.f), wor[nt].y, sA0);
            sA1 = fmaf(fmaxf(acc[nt][2] + b2r[nt].x, 0.f), wor[nt].x, sA1);
            sA1 = fmaf(fmaxf(acc[nt][3] + b2r[nt].y, 0.f), wor[nt].y, sA1);
        }
        sA0 += __shfl_xor_sync(0xffffffffu, sA0, 1);
        sA0 += __shfl_xor_sync(0xffffffffu, sA0, 2);
        sA1 += __shfl_xor_sync(0xffffffffu, sA1, 1);
        sA1 += __shfl_xor_sync(0xffffffffu, sA1, 2);
        if (tid4 == 0) {
            g_T1[(size_t)i * NN + j0 + m0]     = sA0 + bo;
            g_T1[(size_t)i * NN + j0 + m0 + 8] = sA1 + bo;
        }
    }
}

// ---------------------------------------------------------------------------
// Kernel 3: logsumexp + diagonal + fused final reduction.
// 128 blocks x 256 threads; each block handles 8 rows (amortize launch/wave).
// ---------------------------------------------------------------------------
__global__ void lse_kernel(float* out) {
    __shared__ float sm[8], ss[8];
    const int tid = threadIdx.x;
    const int lane = tid & 31, wid = tid >> 5;
    double local = 0.0;

#pragma unroll 1
    for (int r = 0; r < 8; ++r) {
        const int i = blockIdx.x * 8 + r;
        const float4 v = ((const float4*)(g_T1 + (size_t)i * NN))[tid];

        float m = fmaxf(fmaxf(v.x, v.y), fmaxf(v.z, v.w));
#pragma unroll
        for (int o = 16; o > 0; o >>= 1)
            m = fmaxf(m, __shfl_xor_sync(0xffffffffu, m, o));
        if (lane == 0) sm[wid] = m;
        __syncthreads();
        float bm = sm[0];
#pragma unroll
        for (int w = 1; w < 8; ++w) bm = fmaxf(bm, sm[w]);

        float s = __expf(v.x - bm) + __expf(v.y - bm) +
                  __expf(v.z - bm) + __expf(v.w - bm);
#pragma unroll
        for (int o = 16; o > 0; o >>= 1)
            s += __shfl_xor_sync(0xffffffffu, s, o);
        if (lane == 0) ss[wid] = s;
        __syncthreads();

        if (tid == 0) {
            float tot = ss[0] + ss[1] + ss[2] + ss[3] +
                        ss[4] + ss[5] + ss[6] + ss[7];
            local += (double)g_T1[(size_t)i * NN + i]
                   - ((double)bm + log((double)tot));
        }
        __syncthreads();   // sm/ss safe to reuse next row
    }

    if (tid == 0) {
        atomicAdd(&g_acc, local);
        __threadfence();
        if (atomicAdd(&g_cnt, 1) == 127) {
            double acc = atomicAdd(&g_acc, 0.0);   // forced atomic read
            out[0] = (float)(acc / NN + log((double)NN));
        }
    }
}

// ---------------------------------------------------------------------------
extern "C" void kernel_launch(void* const* d_in, const int* in_sizes, int n_in,
                              void* d_out, int out_size) {
    const float* z_c = (const float*)d_in[0];
    const float* z_d = (const float*)d_in[1];
    const float* W1  = (const float*)d_in[2];
    const float* b1  = (const float*)d_in[3];
    const float* W2  = (const float*)d_in[4];
    const float* b2  = (const float*)d_in[5];
    const float* Wo  = (const float*)d_in[6];
    const float* bo  = (const float*)d_in[7];
    float* out = (float*)d_out;

    prep_kernel<<<dim3(NN / 4, 2), 256>>>(z_c, z_d, W1, b1);
    pair_mma_kernel<<<16 * JSTRIDE, 128>>>(W2, b2, Wo, bo);
    lse_kernel<<<128, 256>>>(out);
}

// round 11
// speedup vs baseline: 1.4172x; 1.2356x over previous
#include <cuda_runtime.h>
#include <cuda_fp16.h>
#include <math.h>
#include <stdint.h>

#define NN 1024
#define HH 64

__device__ float g_A[NN * HH];     // z_c @ W1[:64]
__device__ float g_B[NN * HH];     // z_d @ W1[64:] + b1
__device__ float g_T1[NN * NN];
__device__ double g_acc;
__device__ int    g_cnt;

// ---------------------------------------------------------------------------
#define MMA16816(c, a0, a1, a2, a3, b0, b1)                                   \
    asm("mma.sync.aligned.m16n8k16.row.col.f32.f16.f16.f32 "                  \
        "{%0,%1,%2,%3}, {%4,%5,%6,%7}, {%8,%9}, {%0,%1,%2,%3};"               \
        : "+f"((c)[0]), "+f"((c)[1]), "+f"((c)[2]), "+f"((c)[3])              \
        : "r"(a0), "r"(a1), "r"(a2), "r"(a3), "r"(b0), "r"(b1))

__device__ __forceinline__ uint32_t pack_h2(float e0, float e1) {
    uint32_t r;
    asm("cvt.rn.f16x2.f32 %0, %1, %2;" : "=r"(r) : "f"(e1), "f"(e0));
    return r;
}

// ---------------------------------------------------------------------------
// Kernel 1: precompute A and B (R8 form — no smem staging; L1 handles reuse)
// ---------------------------------------------------------------------------
__global__ void prep_kernel(const float* __restrict__ zc,
                            const float* __restrict__ zd,
                            const float* __restrict__ W1,
                            const float* __restrict__ b1) {
    if (blockIdx.x == 0 && blockIdx.y == 0 && threadIdx.x == 0) {
        g_acc = 0.0;
        g_cnt = 0;
    }
    int which = blockIdx.y;
    int row = blockIdx.x * 4 + (threadIdx.x >> 6);
    int col = threadIdx.x & 63;
    const float* src = which ? zd : zc;
    const float* w   = W1 + (which ? 64 * HH : 0);
    float s0 = which ? b1[col] : 0.0f, s1 = 0.f, s2 = 0.f, s3 = 0.f;
#pragma unroll
    for (int k = 0; k < 64; k += 4) {
        s0 = fmaf(src[row * 64 + k],     w[(k) * HH + col],     s0);
        s1 = fmaf(src[row * 64 + k + 1], w[(k + 1) * HH + col], s1);
        s2 = fmaf(src[row * 64 + k + 2], w[(k + 2) * HH + col], s2);
        s3 = fmaf(src[row * 64 + k + 3], w[(k + 3) * HH + col], s3);
    }
    float s = (s0 + s1) + (s2 + s3);
    if (which) g_B[row * HH + col] = s;
    else       g_A[row * HH + col] = s;
}

// ---------------------------------------------------------------------------
// Kernel 2: pairwise MLP via HMMA, single fp16 x fp16 (fp32 accumulate).
// 32 MMAs/iter. Low reg pressure -> occ 3 (3 warps/SMSP hides frag build).
// Bi loads software-pipelined; no smem / no barriers in main loop.
// ---------------------------------------------------------------------------
#define JSTRIDE 27   // CTAs per j-block; grid = 16 * 27 = 432 (1 wave at occ 3)

__global__ __launch_bounds__(128, 3) void pair_mma_kernel(
    const float* __restrict__ W2, const float* __restrict__ b2,
    const float* __restrict__ Wo, const float* __restrict__ bo_p) {
    __shared__ float sAT[64 * 68];   // [k][m], stride 68 (conflict-free frag reads)

    const int tid  = threadIdx.x;
    const int lane = tid & 31;
    const int wid  = tid >> 5;
    const int gid  = lane >> 2;      // 0..7
    const int tid4 = lane & 3;       // 0..3

    const int jb  = blockIdx.x / JSTRIDE;    // 0..15
    const int s0i = blockIdx.x % JSTRIDE;    // starting i
    const int j0  = jb * 64;

    // ---- stage A block transposed: sAT[k*68 + m] = g_A[(j0+m)*64 + k] ----
    for (int idx = tid; idx < 4096; idx += 128) {
        int m = idx >> 6, k = idx & 63;
        sAT[k * 68 + m] = g_A[(size_t)j0 * 64 + idx];
    }

    // ---- preload W2 fragments (fp16) into registers ----
    uint32_t Bf[4][8][2];
#pragma unroll
    for (int ks = 0; ks < 4; ++ks) {
#pragma unroll
        for (int nt = 0; nt < 8; ++nt) {
            int k0 = 16 * ks + 2 * tid4;
            int n  = 8 * nt + gid;
            Bf[ks][nt][0] = pack_h2(W2[(k0 + 0) * HH + n], W2[(k0 + 1) * HH + n]);
            Bf[ks][nt][1] = pack_h2(W2[(k0 + 8) * HH + n], W2[(k0 + 9) * HH + n]);
        }
    }

    // ---- per-thread epilogue constants ----
    float2 b2r[8], wor[8];
#pragma unroll
    for (int nt = 0; nt < 8; ++nt) {
        int n = 8 * nt + 2 * tid4;
        b2r[nt] = make_float2(b2[n], b2[n + 1]);
        wor[nt] = make_float2(Wo[n], Wo[n + 1]);
    }
    const float bo = bo_p[0];

    const int m0 = wid * 16 + gid;   // this thread's first row in j-block

    __syncthreads();                 // sAT ready (only barrier in kernel)

    // ---- prime the Bi pipeline for i = s0i ----
    float2 nbiL[4], nbiH[4];
    {
        const float* Bi = g_B + (size_t)s0i * 64;
#pragma unroll
        for (int ks = 0; ks < 4; ++ks) {
            const int k0 = 16 * ks + 2 * tid4;
            nbiL[ks] = *(const float2*)(Bi + k0);
            nbiH[ks] = *(const float2*)(Bi + k0 + 8);
        }
    }

    for (int i = s0i; i < NN; i += JSTRIDE) {
        float2 biL[4], biH[4];
#pragma unroll
        for (int ks = 0; ks < 4; ++ks) { biL[ks] = nbiL[ks]; biH[ks] = nbiH[ks]; }

        if (i + JSTRIDE < NN) {
            const float* Bn = g_B + (size_t)(i + JSTRIDE) * 64;
#pragma unroll
            for (int ks = 0; ks < 4; ++ks) {
                const int k0 = 16 * ks + 2 * tid4;
                nbiL[ks] = *(const float2*)(Bn + k0);
                nbiH[ks] = *(const float2*)(Bn + k0 + 8);
            }
        }

        float acc[8][4];
#pragma unroll
        for (int nt = 0; nt < 8; ++nt)
#pragma unroll
            for (int q = 0; q < 4; ++q) acc[nt][q] = 0.0f;

#pragma unroll
        for (int ks = 0; ks < 4; ++ks) {
            const int k0 = 16 * ks + 2 * tid4;

            const float* cL = sAT + k0 * 68 + m0;
            float h0 = fmaxf(cL[0]        + biL[ks].x, 0.f);
            float h1 = fmaxf(cL[68]       + biL[ks].y, 0.f);
            float h2 = fmaxf(cL[8 * 68]   + biH[ks].x, 0.f);
            float h3 = fmaxf(cL[9 * 68]   + biH[ks].y, 0.f);
            float h4 = fmaxf(cL[8]        + biL[ks].x, 0.f);
            float h5 = fmaxf(cL[68 + 8]   + biL[ks].y, 0.f);
            float h6 = fmaxf(cL[8*68 + 8] + biH[ks].x, 0.f);
            float h7 = fmaxf(cL[9*68 + 8] + biH[ks].y, 0.f);

            uint32_t a0 = pack_h2(h0, h1);
            uint32_t a1 = pack_h2(h4, h5);
            uint32_t a2 = pack_h2(h2, h3);
            uint32_t a3 = pack_h2(h6, h7);

#pragma unroll
            for (int nt = 0; nt < 8; ++nt)
                MMA16816(acc[nt], a0, a1, a2, a3,
                         Bf[ks][nt][0], Bf[ks][nt][1]);
        }

        // epilogue: rows m0 (c0,c1) and m0+8 (c2,c3)
        float sA0 = 0.f, sA1 = 0.f;
#pragma unroll
        for (int nt = 0; nt < 8; ++nt) {
            sA0 = fmaf(fmaxf(acc[nt][0] + b2r[nt].x, 0.f), wor[nt].x, sA0);
            sA0 = fmaf(fmaxf(acc[nt][1] + b2r[nt].y, 0.f), wor[nt].y, sA0);
            sA1 = fmaf(fmaxf(acc[nt][2] + b2r[nt].x, 0.f), wor[nt].x, sA1);
            sA1 = fmaf(fmaxf(acc[nt][3] + b2r[nt].y, 0.f), wor[nt].y, sA1);
        }
        sA0 += __shfl_xor_sync(0xffffffffu, sA0, 1);
        sA0 += __shfl_xor_sync(0xffffffffu, sA0, 2);
        sA1 += __shfl_xor_sync(0xffffffffu, sA1, 1);
        sA1 += __shfl_xor_sync(0xffffffffu, sA1, 2);
        if (tid4 == 0) {
            g_T1[(size_t)i * NN + j0 + m0]     = sA0 + bo;
            g_T1[(size_t)i * NN + j0 + m0 + 8] = sA1 + bo;
        }
    }
}

// ---------------------------------------------------------------------------
// Kernel 3: logsumexp + diagonal + fused final reduction.
// 128 blocks x 256 threads; each block handles 8 rows.
// ---------------------------------------------------------------------------
__global__ void lse_kernel(float* out) {
    __shared__ float sm[8], ss[8];
    const int tid = threadIdx.x;
    const int lane = tid & 31, wid = tid >> 5;
    double local = 0.0;

#pragma unroll 1
    for (int r = 0; r < 8; ++r) {
        const int i = blockIdx.x * 8 + r;
        const float4 v = ((const float4*)(g_T1 + (size_t)i * NN))[tid];

        float m = fmaxf(fmaxf(v.x, v.y), fmaxf(v.z, v.w));
#pragma unroll
        for (int o = 16; o > 0; o >>= 1)
            m = fmaxf(m, __shfl_xor_sync(0xffffffffu, m, o));
        if (lane == 0) sm[wid] = m;
        __syncthreads();
        float bm = sm[0];
#pragma unroll
        for (int w = 1; w < 8; ++w) bm = fmaxf(bm, sm[w]);

        float s = __expf(v.x - bm) + __expf(v.y - bm) +
                  __expf(v.z - bm) + __expf(v.w - bm);
#pragma unroll
        for (int o = 16; o > 0; o >>= 1)
            s += __shfl_xor_sync(0xffffffffu, s, o);
        if (lane == 0) ss[wid] = s;
        __syncthreads();

        if (tid == 0) {
            float tot = ss[0] + ss[1] + ss[2] + ss[3] +
                        ss[4] + ss[5] + ss[6] + ss[7];
            local += (double)g_T1[(size_t)i * NN + i]
                   - ((double)bm + log((double)tot));
        }
        __syncthreads();   // sm/ss safe to reuse next row
    }

    if (tid == 0) {
        atomicAdd(&g_acc, local);
        __threadfence();
        if (atomicAdd(&g_cnt, 1) == 127) {
            double acc = atomicAdd(&g_acc, 0.0);   // forced atomic read
            out[0] = (float)(acc / NN + log((double)NN));
        }
    }
}

// ---------------------------------------------------------------------------
extern "C" void kernel_launch(void* const* d_in, const int* in_sizes, int n_in,
                              void* d_out, int out_size) {
    const float* z_c = (const float*)d_in[0];
    const float* z_d = (const float*)d_in[1];
    const float* W1  = (const float*)d_in[2];
    const float* b1  = (const float*)d_in[3];
    const float* W2  = (const float*)d_in[4];
    const float* b2  = (const float*)d_in[5];
    const float* Wo  = (const float*)d_in[6];
    const float* bo  = (const float*)d_in[7];
    float* out = (float*)d_out;

    prep_kernel<<<dim3(NN / 4, 2), 256>>>(z_c, z_d, W1, b1);
    pair_mma_kernel<<<16 * JSTRIDE, 128>>>(W2, b2, Wo, bo);
    lse_kernel<<<128, 256>>>(out);
}